// round 9
// baseline (speedup 1.0000x reference)
#include <cuda_runtime.h>

// DigitCaps dynamic routing, fused, G=2, smem-resident u_hat, single-pass
// softmax (no max subtraction: logits bounded |b| < ~40 << 88 overflow),
// routing logits carried in registers across iterations (no smem b[]).
// u:   [B=256, N=1152, IN_C=8]              f32
// W:   [K=10,  N=1152, IN_C=8, OUT_C=16]    f32
// out: [K, B, 1, 1, OUT_C]                  f32
//
// One CTA per (k, batch-pair), 1024 threads (32 warps, 8/scheduler).
// Phase B: lane=(i_sub=lane>>4, o=lane&15); warp covers one n per step with
//   coalesced 128B W reads (4x LDG.32); shfl_xor(16) merges i-halves; lane
//   half i_sub stores batch g=i_sub -> one full-warp conflict-free STS
//   (padded strides: p-stride 4616 = 8 mod 32 banks, g-stride = 4 mod 32).
// Routing iters 1,2: thread-per-n single pass: a = dot16(uh,v) + a_prev
//   (a_prev in registers); e=__expf(a); se+=e; ps+=e*uh (uh regs reused).
//   Warp-reduce ps[16] with a 16-shfl multi-value butterfly, se with 5 shfl.

constexpr int KDIM = 10;
constexpr int BDIM = 256;
constexpr int NDIM = 1152;
constexpr int INC  = 8;
constexpr int OUTC = 16;
constexpr int THREADS = 1024;
constexpr int NWARPS  = THREADS / 32;     // 32
constexpr int G = 2;
constexpr int CTB = BDIM / G;             // 128
constexpr int NPW = NDIM / NWARPS;        // 36 n per warp in phase B (exact)

constexpr int PSTRIDE = NDIM * 4 + 8;     // 4616 floats: 8 mod 32 banks
constexpr int GSTRIDE = 4 * PSTRIDE + 4;  // 18468 floats: 4 mod 32 banks

struct RoutState {
    alignas(16) float vec[G][NWARPS][OUTC];
    float red[G][NWARPS];
    alignas(16) float v[G][OUTC];
};

struct SM {
    alignas(16) float uhm[G * GSTRIDE];   // padded u_hat: 147744 B
    union {
        alignas(16) float u_s[G][2][NDIM * 4];  // deinterleaved u: 73728 B
        RoutState r;
    };
};

__device__ __forceinline__ int UHM(int g, int p, int n) {
    return g * GSTRIDE + p * PSTRIDE + n * 4;
}
__device__ __forceinline__ float dot4(float4 a, float4 b) {
    return fmaf(a.x, b.x, fmaf(a.y, b.y, fmaf(a.z, b.z, a.w * b.w)));
}

__global__ void __launch_bounds__(THREADS)
digitcaps5_kernel(const float* __restrict__ u,
                  const float* __restrict__ W,
                  float* __restrict__ out)
{
    extern __shared__ char smem_raw[];
    SM* sm = reinterpret_cast<SM*>(smem_raw);

    const int kb   = blockIdx.x;
    const int k    = kb / CTB;
    const int bb   = kb % CTB;
    const int t    = threadIdx.x;
    const int w    = t >> 5;
    const int lane = t & 31;
    const int i_sub = lane >> 4;
    const int o     = lane & 15;

    // ---- phase A: stage u, deinterleaved by i parity ----
    {
        const float* ug0 = u + (size_t)(bb * G) * (NDIM * INC);
        const float* ug1 = ug0 + NDIM * INC;
        for (int r = t; r < NDIM; r += THREADS) {
            float4 a0 = *(const float4*)(ug0 + r * 8);
            float4 b0 = *(const float4*)(ug0 + r * 8 + 4);
            *(float4*)&sm->u_s[0][0][r * 4] = make_float4(a0.x, a0.z, b0.x, b0.z);
            *(float4*)&sm->u_s[0][1][r * 4] = make_float4(a0.y, a0.w, b0.y, b0.w);
            float4 a1 = *(const float4*)(ug1 + r * 8);
            float4 b1 = *(const float4*)(ug1 + r * 8 + 4);
            *(float4*)&sm->u_s[1][0][r * 4] = make_float4(a1.x, a1.z, b1.x, b1.z);
            *(float4*)&sm->u_s[1][1][r * 4] = make_float4(a1.y, a1.w, b1.y, b1.w);
        }
    }
    __syncthreads();

    // ---- phase B: u_hat -> smem, + iteration-0 partial sums (uniform c) ----
    float it0_0 = 0.0f, it0_1 = 0.0f;
    {
        const float* Wk = W + (size_t)k * NDIM * (INC * OUTC) + i_sub * OUTC + o;
#pragma unroll 4
        for (int m = 0; m < NPW; m++) {
            const int n = w + NWARPS * m;
            const float* wr = Wk + n * (INC * OUTC);
            float w0 = wr[0], w1 = wr[32], w2 = wr[64], w3 = wr[96];
            float4 ua = *(const float4*)&sm->u_s[0][i_sub][n * 4];
            float4 ub = *(const float4*)&sm->u_s[1][i_sub][n * 4];
            float a0 = fmaf(w0, ua.x, fmaf(w1, ua.y, fmaf(w2, ua.z, w3 * ua.w)));
            float a1 = fmaf(w0, ub.x, fmaf(w1, ub.y, fmaf(w2, ub.z, w3 * ub.w)));
            a0 += __shfl_xor_sync(0xffffffffu, a0, 16);   // merge i halves
            a1 += __shfl_xor_sync(0xffffffffu, a1, 16);
            it0_0 += a0;
            it0_1 += a1;
            // full-warp conflict-free STS: half i_sub stores batch g=i_sub
            sm->uhm[UHM(i_sub, o >> 2, n) + (o & 3)] = (i_sub == 0) ? a0 : a1;
        }
    }
    __syncthreads();   // u_s reads done before union reuse

    if (i_sub == 0) {
        sm->r.vec[0][w][o] = it0_0;
        sm->r.vec[1][w][o] = it0_1;
    }
    __syncthreads();

    // ---- finalize: s = vec-sum / se, squash, store v ----
    auto squash_store = [&](bool use_se, bool write_out) {
        if (t < 2 * OUTC) {                 // warp 0 only
            const int g = t >> 4, oo = t & 15;
            float s = 0.0f, se = 0.0f;
#pragma unroll
            for (int ww = 0; ww < NWARPS; ww++) {
                s += sm->r.vec[g][ww][oo];
                if (use_se) se += sm->r.red[g][ww];
            }
            if (!use_se) se = (float)NDIM;
            s /= se;
            float sq = s * s;
#pragma unroll
            for (int d = 1; d < 16; d <<= 1)
                sq += __shfl_xor_sync(0xffffffffu, sq, d);
            float f  = sqrtf(sq) / (1.0f + sq);
            float vv = s * f;
            sm->r.v[g][oo] = vv;
            if (write_out)
                out[((size_t)k * BDIM + bb * G + g) * OUTC + oo] = vv;
        }
        __syncthreads();
    };

    squash_store(false, false);   // iteration 0

    // routing logits, carried in registers across iterations
    float aold[G][2] = {{0.0f, 0.0f}, {0.0f, 0.0f}};

    // ---- iterations 1..2: single fused pass per g ----
#pragma unroll 1
    for (int it = 1; it < 3; it++) {
#pragma unroll
        for (int g = 0; g < G; g++) {
            float4 v0 = *(const float4*)&sm->r.v[g][0];
            float4 v1 = *(const float4*)&sm->r.v[g][4];
            float4 v2 = *(const float4*)&sm->r.v[g][8];
            float4 v3 = *(const float4*)&sm->r.v[g][12];

            float se = 0.0f;
            float ps[OUTC];
#pragma unroll
            for (int oo = 0; oo < OUTC; oo++) ps[oo] = 0.0f;

#pragma unroll
            for (int q = 0; q < 2; q++) {
                const int n = t + q * THREADS;
                if (n < NDIM) {
                    float4 h0 = *(const float4*)&sm->uhm[UHM(g, 0, n)];
                    float4 h1 = *(const float4*)&sm->uhm[UHM(g, 1, n)];
                    float4 h2 = *(const float4*)&sm->uhm[UHM(g, 2, n)];
                    float4 h3 = *(const float4*)&sm->uhm[UHM(g, 3, n)];
                    float a = (dot4(h0, v0) + dot4(h1, v1)) +
                              (dot4(h2, v2) + dot4(h3, v3)) + aold[g][q];
                    aold[g][q] = a;
                    float e = __expf(a);      // no max-subtract: |a| << 88
                    se += e;
                    ps[0]  = fmaf(e, h0.x, ps[0]);
                    ps[1]  = fmaf(e, h0.y, ps[1]);
                    ps[2]  = fmaf(e, h0.z, ps[2]);
                    ps[3]  = fmaf(e, h0.w, ps[3]);
                    ps[4]  = fmaf(e, h1.x, ps[4]);
                    ps[5]  = fmaf(e, h1.y, ps[5]);
                    ps[6]  = fmaf(e, h1.z, ps[6]);
                    ps[7]  = fmaf(e, h1.w, ps[7]);
                    ps[8]  = fmaf(e, h2.x, ps[8]);
                    ps[9]  = fmaf(e, h2.y, ps[9]);
                    ps[10] = fmaf(e, h2.z, ps[10]);
                    ps[11] = fmaf(e, h2.w, ps[11]);
                    ps[12] = fmaf(e, h3.x, ps[12]);
                    ps[13] = fmaf(e, h3.y, ps[13]);
                    ps[14] = fmaf(e, h3.z, ps[14]);
                    ps[15] = fmaf(e, h3.w, ps[15]);
                }
            }

            // multi-value butterfly: reduce ps[16] across 32 lanes in 16 shfl.
            // final: lanes 2o,2o+1 hold total for channel o.
#pragma unroll
            for (int d = 16, c = 16; d >= 2; d >>= 1, c >>= 1) {
                const bool up = (lane & d) != 0;
                const int half = c >> 1;
#pragma unroll
                for (int i = 0; i < half; i++) {
                    float send = up ? ps[i] : ps[i + half];
                    float keep = up ? ps[i + half] : ps[i];
                    ps[i] = keep + __shfl_xor_sync(0xffffffffu, send, d);
                }
            }
            ps[0] += __shfl_xor_sync(0xffffffffu, ps[0], 1);
            if ((lane & 1) == 0) sm->r.vec[g][w][lane >> 1] = ps[0];

#pragma unroll
            for (int d = 1; d < 32; d <<= 1)
                se += __shfl_xor_sync(0xffffffffu, se, d);
            if (lane == 0) sm->r.red[g][w] = se;
        }
        __syncthreads();
        squash_store(true, it == 2);
    }
}

extern "C" void kernel_launch(void* const* d_in, const int* in_sizes, int n_in,
                              void* d_out, int out_size)
{
    const float* u = (const float*)d_in[0];
    const float* W = (const float*)d_in[1];
    // defensive: identify by element count (u: 2359296, W: 1474560)
    if (n_in >= 2 && in_sizes[0] == KDIM * NDIM * INC * OUTC &&
        in_sizes[1] == BDIM * NDIM * INC) {
        const float* tmp = u; u = W; W = tmp;
    }
    float* out = (float*)d_out;

    cudaFuncSetAttribute(digitcaps5_kernel,
                         cudaFuncAttributeMaxDynamicSharedMemorySize,
                         (int)sizeof(SM));
    digitcaps5_kernel<<<KDIM * CTB, THREADS, sizeof(SM)>>>(u, W, out);
}

// round 12
// speedup vs baseline: 1.1075x; 1.1075x over previous
#include <cuda_runtime.h>

// DigitCaps dynamic routing, fused, G=2, smem-resident u_hat, single-pass
// softmax (no max subtraction: logits bounded |b| < ~40 << 88 overflow),
// routing logits in registers, half-warp batch specialization in routing.
// u:   [B=256, N=1152, IN_C=8]              f32
// W:   [K=10,  N=1152, IN_C=8, OUT_C=16]    f32
// out: [K, B, 1, 1, OUT_C]                  f32
//
// One CTA per (k, batch-pair), 768 threads (24 warps).
// Phase B: lane=(i_sub=lane>>4, o=lane&15); warp covers one n per step with
//   coalesced 128B W reads (4x LDG.32); u broadcast LDS from PADDED staging
//   (i-stride 4612 = 4 mod 32 banks -> conflict-free, was 2-way); shfl_xor(16)
//   merges i-halves; one full-warp conflict-free STS into padded uhm.
// Routing iters 1,2: HALF-WARP g-specialization: lanes 0-15 own g=0, 16-31
//   own g=1; each thread 3 n of its g: a=dot16(uh,v)+a_prev (regs); e=expf;
//   se+=e; ps+=e*uh. ps[16] reduced over 16 lanes in 15 shfl (channel o ->
//   lane o), se in 4 shfl. vec has 16-float inter-g pad so the combined
//   32-lane STS is bank-conflict-free.

constexpr int KDIM = 10;
constexpr int BDIM = 256;
constexpr int NDIM = 1152;
constexpr int INC  = 8;
constexpr int OUTC = 16;
constexpr int THREADS = 768;
constexpr int NWARPS  = THREADS / 32;     // 24
constexpr int G = 2;
constexpr int CTB = BDIM / G;             // 128
constexpr int NPW = NDIM / NWARPS;        // 48 n per warp in phase B
constexpr int HWT = THREADS / 2;          // 384 half-warp threads per g
constexpr int NPH = NDIM / HWT;           // 3 n per thread per g in routing

constexpr int PSTRIDE = NDIM * 4 + 8;     // 4616 floats: 8 mod 32 banks
constexpr int GSTRIDE = 4 * PSTRIDE + 4;  // 18468 floats: 4 mod 32 banks
constexpr int USTRIDE = NDIM * 4 + 4;     // 4612 floats: 4 mod 32 banks (u pad)
constexpr int VSTRIDE = NWARPS * OUTC + 16; // 400 floats: 16 mod 32 banks

struct RoutState {
    float vec[G][VSTRIDE];                // [g][w*16+o], padded between g
    float red[G][NWARPS];
    alignas(16) float v[G][OUTC];
};

struct SM {
    alignas(16) float uhm[G * GSTRIDE];   // padded u_hat: 147744 B
    union {
        alignas(16) float u_s[G][2][USTRIDE];   // deinterleaved u, padded
        RoutState r;
    };
};

__device__ __forceinline__ int UHM(int g, int p, int n) {
    return g * GSTRIDE + p * PSTRIDE + n * 4;
}
__device__ __forceinline__ float dot4(float4 a, float4 b) {
    return fmaf(a.x, b.x, fmaf(a.y, b.y, fmaf(a.z, b.z, a.w * b.w)));
}

__global__ void __launch_bounds__(THREADS)
digitcaps6_kernel(const float* __restrict__ u,
                  const float* __restrict__ W,
                  float* __restrict__ out)
{
    extern __shared__ char smem_raw[];
    SM* sm = reinterpret_cast<SM*>(smem_raw);

    const int kb   = blockIdx.x;
    const int k    = kb / CTB;
    const int bb   = kb % CTB;
    const int t    = threadIdx.x;
    const int w    = t >> 5;
    const int lane = t & 31;
    const int i_sub = lane >> 4;
    const int o     = lane & 15;

    // ---- phase A: stage u, deinterleaved by i parity, padded strides ----
    {
        const float* ug0 = u + (size_t)(bb * G) * (NDIM * INC);
        const float* ug1 = ug0 + NDIM * INC;
        for (int r = t; r < NDIM; r += THREADS) {
            float4 a0 = *(const float4*)(ug0 + r * 8);
            float4 b0 = *(const float4*)(ug0 + r * 8 + 4);
            *(float4*)&sm->u_s[0][0][r * 4] = make_float4(a0.x, a0.z, b0.x, b0.z);
            *(float4*)&sm->u_s[0][1][r * 4] = make_float4(a0.y, a0.w, b0.y, b0.w);
            float4 a1 = *(const float4*)(ug1 + r * 8);
            float4 b1 = *(const float4*)(ug1 + r * 8 + 4);
            *(float4*)&sm->u_s[1][0][r * 4] = make_float4(a1.x, a1.z, b1.x, b1.z);
            *(float4*)&sm->u_s[1][1][r * 4] = make_float4(a1.y, a1.w, b1.y, b1.w);
        }
    }
    __syncthreads();

    // ---- phase B: u_hat -> smem, + iteration-0 partial sums (uniform c) ----
    float it0_0 = 0.0f, it0_1 = 0.0f;
    {
        const float* Wk = W + (size_t)k * NDIM * (INC * OUTC) + i_sub * OUTC + o;
#pragma unroll 4
        for (int m = 0; m < NPW; m++) {
            const int n = w + NWARPS * m;
            const float* wr = Wk + n * (INC * OUTC);
            float w0 = wr[0], w1 = wr[32], w2 = wr[64], w3 = wr[96];
            float4 ua = *(const float4*)&sm->u_s[0][i_sub][n * 4];
            float4 ub = *(const float4*)&sm->u_s[1][i_sub][n * 4];
            float a0 = fmaf(w0, ua.x, fmaf(w1, ua.y, fmaf(w2, ua.z, w3 * ua.w)));
            float a1 = fmaf(w0, ub.x, fmaf(w1, ub.y, fmaf(w2, ub.z, w3 * ub.w)));
            a0 += __shfl_xor_sync(0xffffffffu, a0, 16);   // merge i halves
            a1 += __shfl_xor_sync(0xffffffffu, a1, 16);
            it0_0 += a0;
            it0_1 += a1;
            // full-warp conflict-free STS: half i_sub stores batch g=i_sub
            sm->uhm[UHM(i_sub, o >> 2, n) + (o & 3)] = (i_sub == 0) ? a0 : a1;
        }
    }
    __syncthreads();   // u_s reads done before union reuse

    if (i_sub == 0) {
        sm->r.vec[0][w * OUTC + o] = it0_0;
        sm->r.vec[1][w * OUTC + o] = it0_1;
    }
    __syncthreads();

    // ---- finalize: s = vec-sum / se, squash, store v ----
    auto squash_store = [&](bool use_se, bool write_out) {
        if (t < 2 * OUTC) {                 // warp 0 only
            const int g = t >> 4, oo = t & 15;
            float s = 0.0f, se = 0.0f;
#pragma unroll
            for (int ww = 0; ww < NWARPS; ww++) {
                s += sm->r.vec[g][ww * OUTC + oo];
                if (use_se) se += sm->r.red[g][ww];
            }
            if (!use_se) se = (float)NDIM;
            s /= se;
            float sq = s * s;
#pragma unroll
            for (int d = 1; d < 16; d <<= 1)
                sq += __shfl_xor_sync(0xffffffffu, sq, d);
            float f  = sqrtf(sq) / (1.0f + sq);
            float vv = s * f;
            sm->r.v[g][oo] = vv;
            if (write_out)
                out[((size_t)k * BDIM + bb * G + g) * OUTC + oo] = vv;
        }
        __syncthreads();
    };

    squash_store(false, false);   // iteration 0

    // ---- iterations 1..2: half-warp g-specialization ----
    const int g  = i_sub;          // lanes 0-15 -> g0, 16-31 -> g1
    const int hw = w * 16 + o;     // 0..383 within the g-half
    float aold[NPH] = {0.0f, 0.0f, 0.0f};   // logits in registers

#pragma unroll 1
    for (int it = 1; it < 3; it++) {
        float4 v0 = *(const float4*)&sm->r.v[g][0];
        float4 v1 = *(const float4*)&sm->r.v[g][4];
        float4 v2 = *(const float4*)&sm->r.v[g][8];
        float4 v3 = *(const float4*)&sm->r.v[g][12];

        float se = 0.0f;
        float ps[OUTC];
#pragma unroll
        for (int oo = 0; oo < OUTC; oo++) ps[oo] = 0.0f;

#pragma unroll
        for (int q = 0; q < NPH; q++) {
            const int n = hw + q * HWT;
            float4 h0 = *(const float4*)&sm->uhm[UHM(g, 0, n)];
            float4 h1 = *(const float4*)&sm->uhm[UHM(g, 1, n)];
            float4 h2 = *(const float4*)&sm->uhm[UHM(g, 2, n)];
            float4 h3 = *(const float4*)&sm->uhm[UHM(g, 3, n)];
            float a = (dot4(h0, v0) + dot4(h1, v1)) +
                      (dot4(h2, v2) + dot4(h3, v3)) + aold[q];
            aold[q] = a;
            float e = __expf(a);          // no max-subtract: |a| << 88
            se += e;
            ps[0]  = fmaf(e, h0.x, ps[0]);
            ps[1]  = fmaf(e, h0.y, ps[1]);
            ps[2]  = fmaf(e, h0.z, ps[2]);
            ps[3]  = fmaf(e, h0.w, ps[3]);
            ps[4]  = fmaf(e, h1.x, ps[4]);
            ps[5]  = fmaf(e, h1.y, ps[5]);
            ps[6]  = fmaf(e, h1.z, ps[6]);
            ps[7]  = fmaf(e, h1.w, ps[7]);
            ps[8]  = fmaf(e, h2.x, ps[8]);
            ps[9]  = fmaf(e, h2.y, ps[9]);
            ps[10] = fmaf(e, h2.z, ps[10]);
            ps[11] = fmaf(e, h2.w, ps[11]);
            ps[12] = fmaf(e, h3.x, ps[12]);
            ps[13] = fmaf(e, h3.y, ps[13]);
            ps[14] = fmaf(e, h3.z, ps[14]);
            ps[15] = fmaf(e, h3.w, ps[15]);
        }

        // multi-value butterfly over the 16-lane half-warp: 15 shfl.
        // Binds channel bit log2(d) to lane bit log2(d): channel o -> lane o.
#pragma unroll
        for (int d = 8, c = 16; d >= 1; d >>= 1, c >>= 1) {
            const bool up = (lane & d) != 0;
            const int half = c >> 1;
#pragma unroll
            for (int i = 0; i < half; i++) {
                float send = up ? ps[i] : ps[i + half];
                float keep = up ? ps[i + half] : ps[i];
                ps[i] = keep + __shfl_xor_sync(0xffffffffu, send, d);
            }
        }
        // combined 32-lane STS: g-halves hit disjoint banks (VSTRIDE pad)
        sm->r.vec[g][w * OUTC + o] = ps[0];

#pragma unroll
        for (int d = 1; d < 16; d <<= 1)
            se += __shfl_xor_sync(0xffffffffu, se, d);
        if (o == 0) sm->r.red[g][w] = se;

        __syncthreads();
        squash_store(true, it == 2);
    }
}

extern "C" void kernel_launch(void* const* d_in, const int* in_sizes, int n_in,
                              void* d_out, int out_size)
{
    const float* u = (const float*)d_in[0];
    const float* W = (const float*)d_in[1];
    // defensive: identify by element count (u: 2359296, W: 1474560)
    if (n_in >= 2 && in_sizes[0] == KDIM * NDIM * INC * OUTC &&
        in_sizes[1] == BDIM * NDIM * INC) {
        const float* tmp = u; u = W; W = tmp;
    }
    float* out = (float*)d_out;

    cudaFuncSetAttribute(digitcaps6_kernel,
                         cudaFuncAttributeMaxDynamicSharedMemorySize,
                         (int)sizeof(SM));
    digitcaps6_kernel<<<KDIM * CTB, THREADS, sizeof(SM)>>>(u, W, out);
}

// round 14
// speedup vs baseline: 1.2595x; 1.1372x over previous
#include <cuda_runtime.h>

// DigitCaps dynamic routing, TWO-KERNEL version.
// k1: u_hat = einsum('bni,knio->kbno') as a smem-tiled register-blocked GEMM,
//     written to a __device__ scratch in transposed layout [k][b][p][n][4]
//     (p = o>>2) so k2 can copy it straight into its padded smem layout.
// k2: per-(k,b) routing: copy slice to smem (+iter-0 sums on the fly),
//     2 fused routing iterations (single-pass softmax, no max-subtract:
//     logits bounded |b| < ~40 << 88), squash, store.
//
// u:   [B=256, N=1152, IN_C=8]              f32
// W:   [K=10,  N=1152, IN_C=8, OUT_C=16]    f32
// out: [K, B, 1, 1, OUT_C]                  f32

constexpr int KDIM = 10;
constexpr int BDIM = 256;
constexpr int NDIM = 1152;
constexpr int INC  = 8;
constexpr int OUTC = 16;

// ---------------- scratch: u_hat [k][b][p(=o>>2)][n][4] ----------------
__device__ float uhat_g[(size_t)KDIM * BDIM * 4 * NDIM * 4];

// ======================= kernel 1: u_hat GEMM ==========================
constexpr int K1_THREADS = 512;
constexpr int BT = 128;            // b-tile
constexpr int NC = 16;             // n-chunk
constexpr int URow = 132;          // padded u_sm row (16n*8i + 4)
constexpr int WRow = 132;          // padded w_sm row (8i*16o + 4)

struct SM1 {
    alignas(16) float u_sm[BT * URow];   // 67584 B
    alignas(16) float w_sm[NC * WRow];   //  8448 B
};

__global__ void __launch_bounds__(K1_THREADS, 2)
uhat_kernel(const float* __restrict__ u, const float* __restrict__ W)
{
    extern __shared__ char smem_raw[];
    SM1* sm = reinterpret_cast<SM1*>(smem_raw);
    const int t  = threadIdx.x;
    const int n0 = blockIdx.x * NC;
    const int b0 = blockIdx.y * BT;
    const int k  = blockIdx.z;

    // load W chunk: W[k][n0..+16][8][16] = 512 float4, one per thread
    {
        const int n = t >> 5, idx = t & 31;
        float4 v = *(const float4*)(W + ((size_t)k * NDIM + n0 + n) * 128 + idx * 4);
        *(float4*)&sm->w_sm[n * WRow + idx * 4] = v;
    }
    // load u tile: u[b0..+128][n0..+16][8] = 4096 float4, 8 per thread
#pragma unroll
    for (int r = 0; r < 8; r++) {
        const int f = t + K1_THREADS * r;
        const int b = f >> 5, idx = f & 31;
        float4 v = *(const float4*)(u + ((size_t)(b0 + b) * NDIM + n0) * INC + idx * 4);
        *(float4*)&sm->u_sm[b * URow + idx * 4] = v;
    }
    __syncthreads();

    const int n  = t & 15;
    const int oq = (t >> 4) & 3;
    const int bb = t >> 6;            // 0..7, each handles 16 b's

    // W quad for this (n, oq): 8 i-rows of 4 o's, register-resident
    float4 wq[INC];
#pragma unroll
    for (int i = 0; i < INC; i++)
        wq[i] = *(const float4*)&sm->w_sm[n * WRow + i * OUTC + oq * 4];

    float* dst_base = uhat_g +
        (((size_t)(k * BDIM + b0) * 4 + oq) * NDIM + (n0 + n)) * 4;

#pragma unroll 4
    for (int bi = 0; bi < 16; bi++) {
        const int b = bb * 16 + bi;
        float4 ua = *(const float4*)&sm->u_sm[b * URow + n * INC];      // i 0..3
        float4 ub = *(const float4*)&sm->u_sm[b * URow + n * INC + 4];  // i 4..7
        float4 acc;
        acc.x = ua.x * wq[0].x; acc.y = ua.x * wq[0].y;
        acc.z = ua.x * wq[0].z; acc.w = ua.x * wq[0].w;
        acc.x = fmaf(ua.y, wq[1].x, acc.x); acc.y = fmaf(ua.y, wq[1].y, acc.y);
        acc.z = fmaf(ua.y, wq[1].z, acc.z); acc.w = fmaf(ua.y, wq[1].w, acc.w);
        acc.x = fmaf(ua.z, wq[2].x, acc.x); acc.y = fmaf(ua.z, wq[2].y, acc.y);
        acc.z = fmaf(ua.z, wq[2].z, acc.z); acc.w = fmaf(ua.z, wq[2].w, acc.w);
        acc.x = fmaf(ua.w, wq[3].x, acc.x); acc.y = fmaf(ua.w, wq[3].y, acc.y);
        acc.z = fmaf(ua.w, wq[3].z, acc.z); acc.w = fmaf(ua.w, wq[3].w, acc.w);
        acc.x = fmaf(ub.x, wq[4].x, acc.x); acc.y = fmaf(ub.x, wq[4].y, acc.y);
        acc.z = fmaf(ub.x, wq[4].z, acc.z); acc.w = fmaf(ub.x, wq[4].w, acc.w);
        acc.x = fmaf(ub.y, wq[5].x, acc.x); acc.y = fmaf(ub.y, wq[5].y, acc.y);
        acc.z = fmaf(ub.y, wq[5].z, acc.z); acc.w = fmaf(ub.y, wq[5].w, acc.w);
        acc.x = fmaf(ub.z, wq[6].x, acc.x); acc.y = fmaf(ub.z, wq[6].y, acc.y);
        acc.z = fmaf(ub.z, wq[6].z, acc.z); acc.w = fmaf(ub.z, wq[6].w, acc.w);
        acc.x = fmaf(ub.w, wq[7].x, acc.x); acc.y = fmaf(ub.w, wq[7].y, acc.y);
        acc.z = fmaf(ub.w, wq[7].z, acc.z); acc.w = fmaf(ub.w, wq[7].w, acc.w);
        // [k][b][oq][n][4]; b stride = 4*NDIM*4 floats
        *(float4*)(dst_base + (size_t)b * 4 * NDIM * 4) = acc;
    }
}

// ======================= kernel 2: routing =============================
constexpr int K2_THREADS = 576;
constexpr int K2_WARPS   = K2_THREADS / 32;   // 18
constexpr int NPH2 = NDIM / K2_THREADS;       // 2 n per thread
constexpr int PST2 = NDIM * 4 + 8;            // 4616: p-plane stride, 8 mod 32

struct SM2 {
    alignas(16) float uhm[4 * PST2];          // 73856 B
    alignas(16) float vec[K2_WARPS * OUTC];   // per-warp ps partials
    float red[K2_WARPS];                      // per-warp se partials
    alignas(16) float v[OUTC];
};

__device__ __forceinline__ float dot4_(float4 a, float4 b) {
    return fmaf(a.x, b.x, fmaf(a.y, b.y, fmaf(a.z, b.z, a.w * b.w)));
}

__global__ void __launch_bounds__(K2_THREADS, 2)
routing_kernel(float* __restrict__ out)
{
    extern __shared__ char smem_raw[];
    SM2* sm = reinterpret_cast<SM2*>(smem_raw);
    const int kb   = blockIdx.x;           // k*256 + b
    const int t    = threadIdx.x;
    const int w    = t >> 5;
    const int lane = t & 31;

    // ---- copy slice to smem + iteration-0 accumulation ----
    const float4* src = reinterpret_cast<const float4*>(
        uhat_g + (size_t)kb * 4 * NDIM * 4);
    float acc[OUTC];
#pragma unroll
    for (int oo = 0; oo < OUTC; oo++) acc[oo] = 0.0f;

#pragma unroll
    for (int r = 0; r < 8; r++) {          // 4608 float4 / 576 threads
        const int p = r >> 1;
        const int n = t + (r & 1) * K2_THREADS;
        float4 val = src[p * NDIM + n];
        *(float4*)&sm->uhm[p * PST2 + n * 4] = val;
        acc[p * 4 + 0] += val.x;
        acc[p * 4 + 1] += val.y;
        acc[p * 4 + 2] += val.z;
        acc[p * 4 + 3] += val.w;
    }

    // multi-value butterfly: 16 values over 32 lanes; channel o -> lanes 2o,2o+1
#pragma unroll
    for (int d = 16, c = 16; d >= 2; d >>= 1, c >>= 1) {
        const bool up = (lane & d) != 0;
        const int half = c >> 1;
#pragma unroll
        for (int i = 0; i < half; i++) {
            float send = up ? acc[i] : acc[i + half];
            float keep = up ? acc[i + half] : acc[i];
            acc[i] = keep + __shfl_xor_sync(0xffffffffu, send, d);
        }
    }
    acc[0] += __shfl_xor_sync(0xffffffffu, acc[0], 1);
    if ((lane & 1) == 0) sm->vec[w * OUTC + (lane >> 1)] = acc[0];
    __syncthreads();

    // ---- squash helper (warp 0) ----
    auto squash_store = [&](bool use_se, bool write_out) {
        if (t < 32) {
            const int oo = t & 15;         // both 16-lane halves identical
            float s = 0.0f, se = 0.0f;
#pragma unroll
            for (int ww = 0; ww < K2_WARPS; ww++) {
                s += sm->vec[ww * OUTC + oo];
                if (use_se) se += sm->red[ww];
            }
            if (!use_se) se = (float)NDIM;
            s /= se;
            float sq = s * s;
#pragma unroll
            for (int d = 1; d < 16; d <<= 1)
                sq += __shfl_xor_sync(0xffffffffu, sq, d);
            float f  = sqrtf(sq) / (1.0f + sq);
            float vv = s * f;
            if (t < OUTC) {
                sm->v[oo] = vv;
                if (write_out) out[(size_t)kb * OUTC + oo] = vv;
            }
        }
        __syncthreads();
    };

    squash_store(false, false);            // iteration 0

    float aold[NPH2] = {0.0f, 0.0f};       // routing logits in registers

#pragma unroll 1
    for (int it = 1; it < 3; it++) {
        float4 v0 = *(const float4*)&sm->v[0];
        float4 v1 = *(const float4*)&sm->v[4];
        float4 v2 = *(const float4*)&sm->v[8];
        float4 v3 = *(const float4*)&sm->v[12];

        float se = 0.0f;
        float ps[OUTC];
#pragma unroll
        for (int oo = 0; oo < OUTC; oo++) ps[oo] = 0.0f;

#pragma unroll
        for (int q = 0; q < NPH2; q++) {
            const int n = t + q * K2_THREADS;
            float4 h0 = *(const float4*)&sm->uhm[0 * PST2 + n * 4];
            float4 h1 = *(const float4*)&sm->uhm[1 * PST2 + n * 4];
            float4 h2 = *(const float4*)&sm->uhm[2 * PST2 + n * 4];
            float4 h3 = *(const float4*)&sm->uhm[3 * PST2 + n * 4];
            float a = (dot4_(h0, v0) + dot4_(h1, v1)) +
                      (dot4_(h2, v2) + dot4_(h3, v3)) + aold[q];
            aold[q] = a;
            float e = __expf(a);           // no max-subtract: |a| << 88
            se += e;
            ps[0]  = fmaf(e, h0.x, ps[0]);
            ps[1]  = fmaf(e, h0.y, ps[1]);
            ps[2]  = fmaf(e, h0.z, ps[2]);
            ps[3]  = fmaf(e, h0.w, ps[3]);
            ps[4]  = fmaf(e, h1.x, ps[4]);
            ps[5]  = fmaf(e, h1.y, ps[5]);
            ps[6]  = fmaf(e, h1.z, ps[6]);
            ps[7]  = fmaf(e, h1.w, ps[7]);
            ps[8]  = fmaf(e, h2.x, ps[8]);
            ps[9]  = fmaf(e, h2.y, ps[9]);
            ps[10] = fmaf(e, h2.z, ps[10]);
            ps[11] = fmaf(e, h2.w, ps[11]);
            ps[12] = fmaf(e, h3.x, ps[12]);
            ps[13] = fmaf(e, h3.y, ps[13]);
            ps[14] = fmaf(e, h3.z, ps[14]);
            ps[15] = fmaf(e, h3.w, ps[15]);
        }

        // 16-value butterfly over 32 lanes (16 shfl); channel o -> lanes 2o
#pragma unroll
        for (int d = 16, c = 16; d >= 2; d >>= 1, c >>= 1) {
            const bool up = (lane & d) != 0;
            const int half = c >> 1;
#pragma unroll
            for (int i = 0; i < half; i++) {
                float send = up ? ps[i] : ps[i + half];
                float keep = up ? ps[i + half] : ps[i];
                ps[i] = keep + __shfl_xor_sync(0xffffffffu, send, d);
            }
        }
        ps[0] += __shfl_xor_sync(0xffffffffu, ps[0], 1);
        if ((lane & 1) == 0) sm->vec[w * OUTC + (lane >> 1)] = ps[0];

#pragma unroll
        for (int d = 1; d < 32; d <<= 1)
            se += __shfl_xor_sync(0xffffffffu, se, d);
        if (lane == 0) sm->red[w] = se;

        __syncthreads();
        squash_store(true, it == 2);
    }
}

// ============================ launch ===================================
extern "C" void kernel_launch(void* const* d_in, const int* in_sizes, int n_in,
                              void* d_out, int out_size)
{
    const float* u = (const float*)d_in[0];
    const float* W = (const float*)d_in[1];
    // defensive: identify by element count (u: 2359296, W: 1474560)
    if (n_in >= 2 && in_sizes[0] == KDIM * NDIM * INC * OUTC &&
        in_sizes[1] == BDIM * NDIM * INC) {
        const float* tmp = u; u = W; W = tmp;
    }
    float* out = (float*)d_out;

    cudaFuncSetAttribute(uhat_kernel,
                         cudaFuncAttributeMaxDynamicSharedMemorySize,
                         (int)sizeof(SM1));
    cudaFuncSetAttribute(routing_kernel,
                         cudaFuncAttributeMaxDynamicSharedMemorySize,
                         (int)sizeof(SM2));

    dim3 g1(NDIM / NC, BDIM / BT, KDIM);   // (72, 2, 10)
    uhat_kernel<<<g1, K1_THREADS, sizeof(SM1)>>>(u, W);
    routing_kernel<<<KDIM * BDIM, K2_THREADS, sizeof(SM2)>>>(out);
}

// round 15
// speedup vs baseline: 1.4269x; 1.1329x over previous
#include <cuda_runtime.h>
#include <cuda_fp16.h>

// DigitCaps dynamic routing, TWO-KERNEL version with fp16 u_hat scratch.
// k1: u_hat = einsum('bni,knio->kbno'), smem-tiled register-blocked GEMM,
//     results converted to fp16 and written to a __device__ scratch in
//     layout [k][b][p(=o>>2)][n] of uint2 (4 halves per group).
//     94.5 MB < 126 MB L2 -> k2's reads are mostly L2 hits.
// k2: per-(k,b) routing: copy fp16 slice to fp32 smem (+iter-0 sums on the
//     fly), 2 fused routing iterations (single-pass softmax, no max-subtract:
//     logits bounded |b| < ~40 << 88), squash, store. All math fp32.
//
// u:   [B=256, N=1152, IN_C=8]              f32
// W:   [K=10,  N=1152, IN_C=8, OUT_C=16]    f32
// out: [K, B, 1, 1, OUT_C]                  f32

constexpr int KDIM = 10;
constexpr int BDIM = 256;
constexpr int NDIM = 1152;
constexpr int INC  = 8;
constexpr int OUTC = 16;

// ---------- scratch: u_hat fp16, [k][b][p][n] as uint2 (4 halves) ----------
__device__ uint2 uhat_g[(size_t)KDIM * BDIM * 4 * NDIM];

// ======================= kernel 1: u_hat GEMM ==========================
constexpr int K1_THREADS = 512;
constexpr int BT = 128;            // b-tile
constexpr int NC = 16;             // n-chunk
constexpr int URow = 132;          // padded u_sm row (16n*8i + 4)
constexpr int WRow = 132;          // padded w_sm row (8i*16o + 4)

struct SM1 {
    alignas(16) float u_sm[BT * URow];   // 67584 B
    alignas(16) float w_sm[NC * WRow];   //  8448 B
};

__global__ void __launch_bounds__(K1_THREADS, 2)
uhat_kernel(const float* __restrict__ u, const float* __restrict__ W)
{
    extern __shared__ char smem_raw[];
    SM1* sm = reinterpret_cast<SM1*>(smem_raw);
    const int t  = threadIdx.x;
    const int n0 = blockIdx.x * NC;
    const int b0 = blockIdx.y * BT;
    const int k  = blockIdx.z;

    // load W chunk: W[k][n0..+16][8][16] = 512 float4, one per thread
    {
        const int n = t >> 5, idx = t & 31;
        float4 v = *(const float4*)(W + ((size_t)k * NDIM + n0 + n) * 128 + idx * 4);
        *(float4*)&sm->w_sm[n * WRow + idx * 4] = v;
    }
    // load u tile: u[b0..+128][n0..+16][8] = 4096 float4, 8 per thread
#pragma unroll
    for (int r = 0; r < 8; r++) {
        const int f = t + K1_THREADS * r;
        const int b = f >> 5, idx = f & 31;
        float4 v = *(const float4*)(u + ((size_t)(b0 + b) * NDIM + n0) * INC + idx * 4);
        *(float4*)&sm->u_sm[b * URow + idx * 4] = v;
    }
    __syncthreads();

    const int n  = t & 15;
    const int oq = (t >> 4) & 3;
    const int bb = t >> 6;            // 0..7, each handles 16 b's

    // W quad for this (n, oq): 8 i-rows of 4 o's, register-resident
    float4 wq[INC];
#pragma unroll
    for (int i = 0; i < INC; i++)
        wq[i] = *(const float4*)&sm->w_sm[n * WRow + i * OUTC + oq * 4];

    uint2* dst_base = uhat_g +
        ((size_t)(k * BDIM + b0) * 4 + oq) * NDIM + (n0 + n);

#pragma unroll 4
    for (int bi = 0; bi < 16; bi++) {
        const int b = bb * 16 + bi;
        float4 ua = *(const float4*)&sm->u_sm[b * URow + n * INC];      // i 0..3
        float4 ub = *(const float4*)&sm->u_sm[b * URow + n * INC + 4];  // i 4..7
        float4 acc;
        acc.x = ua.x * wq[0].x; acc.y = ua.x * wq[0].y;
        acc.z = ua.x * wq[0].z; acc.w = ua.x * wq[0].w;
        acc.x = fmaf(ua.y, wq[1].x, acc.x); acc.y = fmaf(ua.y, wq[1].y, acc.y);
        acc.z = fmaf(ua.y, wq[1].z, acc.z); acc.w = fmaf(ua.y, wq[1].w, acc.w);
        acc.x = fmaf(ua.z, wq[2].x, acc.x); acc.y = fmaf(ua.z, wq[2].y, acc.y);
        acc.z = fmaf(ua.z, wq[2].z, acc.z); acc.w = fmaf(ua.z, wq[2].w, acc.w);
        acc.x = fmaf(ua.w, wq[3].x, acc.x); acc.y = fmaf(ua.w, wq[3].y, acc.y);
        acc.z = fmaf(ua.w, wq[3].z, acc.z); acc.w = fmaf(ua.w, wq[3].w, acc.w);
        acc.x = fmaf(ub.x, wq[4].x, acc.x); acc.y = fmaf(ub.x, wq[4].y, acc.y);
        acc.z = fmaf(ub.x, wq[4].z, acc.z); acc.w = fmaf(ub.x, wq[4].w, acc.w);
        acc.x = fmaf(ub.y, wq[5].x, acc.x); acc.y = fmaf(ub.y, wq[5].y, acc.y);
        acc.z = fmaf(ub.y, wq[5].z, acc.z); acc.w = fmaf(ub.y, wq[5].w, acc.w);
        acc.x = fmaf(ub.z, wq[6].x, acc.x); acc.y = fmaf(ub.z, wq[6].y, acc.y);
        acc.z = fmaf(ub.z, wq[6].z, acc.z); acc.w = fmaf(ub.z, wq[6].w, acc.w);
        acc.x = fmaf(ub.w, wq[7].x, acc.x); acc.y = fmaf(ub.w, wq[7].y, acc.y);
        acc.z = fmaf(ub.w, wq[7].z, acc.z); acc.w = fmaf(ub.w, wq[7].w, acc.w);
        // fp16 pack: 4 halves = uint2
        __half2 h01 = __float22half2_rn(make_float2(acc.x, acc.y));
        __half2 h23 = __float22half2_rn(make_float2(acc.z, acc.w));
        uint2 pack;
        pack.x = *reinterpret_cast<unsigned int*>(&h01);
        pack.y = *reinterpret_cast<unsigned int*>(&h23);
        // [k][b][oq][n]; b stride = 4*NDIM uint2
        dst_base[(size_t)b * 4 * NDIM] = pack;
    }
}

// ======================= kernel 2: routing =============================
constexpr int K2_THREADS = 576;
constexpr int K2_WARPS   = K2_THREADS / 32;   // 18
constexpr int NPH2 = NDIM / K2_THREADS;       // 2 n per thread
constexpr int PST2 = NDIM * 4 + 8;            // 4616: p-plane stride, 8 mod 32

struct SM2 {
    alignas(16) float uhm[4 * PST2];          // 73856 B (fp32 after convert)
    alignas(16) float vec[K2_WARPS * OUTC];   // per-warp ps partials
    float red[K2_WARPS];                      // per-warp se partials
    alignas(16) float v[OUTC];
};

__device__ __forceinline__ float dot4_(float4 a, float4 b) {
    return fmaf(a.x, b.x, fmaf(a.y, b.y, fmaf(a.z, b.z, a.w * b.w)));
}

__global__ void __launch_bounds__(K2_THREADS, 2)
routing_kernel(float* __restrict__ out)
{
    extern __shared__ char smem_raw[];
    SM2* sm = reinterpret_cast<SM2*>(smem_raw);
    const int kb   = blockIdx.x;           // k*256 + b
    const int t    = threadIdx.x;
    const int w    = t >> 5;
    const int lane = t & 31;

    // ---- copy fp16 slice -> fp32 smem + iteration-0 accumulation ----
    const uint2* src = uhat_g + (size_t)kb * 4 * NDIM;
    float acc[OUTC];
#pragma unroll
    for (int oo = 0; oo < OUTC; oo++) acc[oo] = 0.0f;

#pragma unroll
    for (int r = 0; r < 8; r++) {          // 4608 uint2 / 576 threads
        const int p = r >> 1;
        const int n = t + (r & 1) * K2_THREADS;
        uint2 raw = src[p * NDIM + n];
        __half2 h01 = *reinterpret_cast<__half2*>(&raw.x);
        __half2 h23 = *reinterpret_cast<__half2*>(&raw.y);
        float2 f01 = __half22float2(h01);
        float2 f23 = __half22float2(h23);
        float4 val = make_float4(f01.x, f01.y, f23.x, f23.y);
        *(float4*)&sm->uhm[p * PST2 + n * 4] = val;
        acc[p * 4 + 0] += val.x;
        acc[p * 4 + 1] += val.y;
        acc[p * 4 + 2] += val.z;
        acc[p * 4 + 3] += val.w;
    }

    // multi-value butterfly: 16 values over 32 lanes; channel o -> lanes 2o,2o+1
#pragma unroll
    for (int d = 16, c = 16; d >= 2; d >>= 1, c >>= 1) {
        const bool up = (lane & d) != 0;
        const int half = c >> 1;
#pragma unroll
        for (int i = 0; i < half; i++) {
            float send = up ? acc[i] : acc[i + half];
            float keep = up ? acc[i + half] : acc[i];
            acc[i] = keep + __shfl_xor_sync(0xffffffffu, send, d);
        }
    }
    acc[0] += __shfl_xor_sync(0xffffffffu, acc[0], 1);
    if ((lane & 1) == 0) sm->vec[w * OUTC + (lane >> 1)] = acc[0];
    __syncthreads();

    // ---- squash helper (warp 0) ----
    auto squash_store = [&](bool use_se, bool write_out) {
        if (t < 32) {
            const int oo = t & 15;         // both 16-lane halves identical
            float s = 0.0f, se = 0.0f;
#pragma unroll
            for (int ww = 0; ww < K2_WARPS; ww++) {
                s += sm->vec[ww * OUTC + oo];
                if (use_se) se += sm->red[ww];
            }
            if (!use_se) se = (float)NDIM;
            s /= se;
            float sq = s * s;
#pragma unroll
            for (int d = 1; d < 16; d <<= 1)
                sq += __shfl_xor_sync(0xffffffffu, sq, d);
            float f  = sqrtf(sq) / (1.0f + sq);
            float vv = s * f;
            if (t < OUTC) {
                sm->v[oo] = vv;
                if (write_out) out[(size_t)kb * OUTC + oo] = vv;
            }
        }
        __syncthreads();
    };

    squash_store(false, false);            // iteration 0

    float aold[NPH2] = {0.0f, 0.0f};       // routing logits in registers

#pragma unroll 1
    for (int it = 1; it < 3; it++) {
        float4 v0 = *(const float4*)&sm->v[0];
        float4 v1 = *(const float4*)&sm->v[4];
        float4 v2 = *(const float4*)&sm->v[8];
        float4 v3 = *(const float4*)&sm->v[12];

        float se = 0.0f;
        float ps[OUTC];
#pragma unroll
        for (int oo = 0; oo < OUTC; oo++) ps[oo] = 0.0f;

#pragma unroll
        for (int q = 0; q < NPH2; q++) {
            const int n = t + q * K2_THREADS;
            float4 h0 = *(const float4*)&sm->uhm[0 * PST2 + n * 4];
            float4 h1 = *(const float4*)&sm->uhm[1 * PST2 + n * 4];
            float4 h2 = *(const float4*)&sm->uhm[2 * PST2 + n * 4];
            float4 h3 = *(const float4*)&sm->uhm[3 * PST2 + n * 4];
            float a = (dot4_(h0, v0) + dot4_(h1, v1)) +
                      (dot4_(h2, v2) + dot4_(h3, v3)) + aold[q];
            aold[q] = a;
            float e = __expf(a);           // no max-subtract: |a| << 88
            se += e;
            ps[0]  = fmaf(e, h0.x, ps[0]);
            ps[1]  = fmaf(e, h0.y, ps[1]);
            ps[2]  = fmaf(e, h0.z, ps[2]);
            ps[3]  = fmaf(e, h0.w, ps[3]);
            ps[4]  = fmaf(e, h1.x, ps[4]);
            ps[5]  = fmaf(e, h1.y, ps[5]);
            ps[6]  = fmaf(e, h1.z, ps[6]);
            ps[7]  = fmaf(e, h1.w, ps[7]);
            ps[8]  = fmaf(e, h2.x, ps[8]);
            ps[9]  = fmaf(e, h2.y, ps[9]);
            ps[10] = fmaf(e, h2.z, ps[10]);
            ps[11] = fmaf(e, h2.w, ps[11]);
            ps[12] = fmaf(e, h3.x, ps[12]);
            ps[13] = fmaf(e, h3.y, ps[13]);
            ps[14] = fmaf(e, h3.z, ps[14]);
            ps[15] = fmaf(e, h3.w, ps[15]);
        }

        // 16-value butterfly over 32 lanes (16 shfl); channel o -> lanes 2o
#pragma unroll
        for (int d = 16, c = 16; d >= 2; d >>= 1, c >>= 1) {
            const bool up = (lane & d) != 0;
            const int half = c >> 1;
#pragma unroll
            for (int i = 0; i < half; i++) {
                float send = up ? ps[i] : ps[i + half];
                float keep = up ? ps[i + half] : ps[i];
                ps[i] = keep + __shfl_xor_sync(0xffffffffu, send, d);
            }
        }
        ps[0] += __shfl_xor_sync(0xffffffffu, ps[0], 1);
        if ((lane & 1) == 0) sm->vec[w * OUTC + (lane >> 1)] = ps[0];

#pragma unroll
        for (int d = 1; d < 32; d <<= 1)
            se += __shfl_xor_sync(0xffffffffu, se, d);
        if (lane == 0) sm->red[w] = se;

        __syncthreads();
        squash_store(true, it == 2);
    }
}

// ============================ launch ===================================
extern "C" void kernel_launch(void* const* d_in, const int* in_sizes, int n_in,
                              void* d_out, int out_size)
{
    const float* u = (const float*)d_in[0];
    const float* W = (const float*)d_in[1];
    // defensive: identify by element count (u: 2359296, W: 1474560)
    if (n_in >= 2 && in_sizes[0] == KDIM * NDIM * INC * OUTC &&
        in_sizes[1] == BDIM * NDIM * INC) {
        const float* tmp = u; u = W; W = tmp;
    }
    float* out = (float*)d_out;

    cudaFuncSetAttribute(uhat_kernel,
                         cudaFuncAttributeMaxDynamicSharedMemorySize,
                         (int)sizeof(SM1));
    cudaFuncSetAttribute(routing_kernel,
                         cudaFuncAttributeMaxDynamicSharedMemorySize,
                         (int)sizeof(SM2));

    dim3 g1(NDIM / NC, BDIM / BT, KDIM);   // (72, 2, 10)
    uhat_kernel<<<g1, K1_THREADS, sizeof(SM1)>>>(u, W);
    routing_kernel<<<KDIM * BDIM, K2_THREADS, sizeof(SM2)>>>(out);
}